// round 11
// baseline (speedup 1.0000x reference)
#include <cuda_runtime.h>

#define N 8192
#define ROWS_PER_BLK 64
#define COLS_PER_BLK 1024
#define CB 8      /* column tiles: 8192/1024 */
#define RB 128    /* row tiles:    8192/64   */
#define THREADS 256

#define FXSCALE 16777216.f          /* 2^24 fixed-point scale */
#define FXINV   (1.f / 16777216.f)

// Fixed-point accumulators (order-invariant integer adds -> deterministic).
// Zero-initialized statically; epilogue re-zeroes them for graph replays.
__device__ unsigned long long g_colsum[N];   // 64 KB
__device__ unsigned long long g_rowsum[N];   // 64 KB

__device__ __forceinline__ void fx_add(unsigned long long* p, float v)
{
    atomicAdd(p, (unsigned long long)(long long)__float2ll_rn(v * FXSCALE));
}

// ---------------------------------------------------------------------------
// Pass 1: one block per 64x1024 tile -> 1024 blocks (proven geometry).
// Streaming single read of the 256 MiB matrix. Partials go straight into
// int64 fixed-point accumulators via REDG (no 4 MiB scratch round-trip).
// ---------------------------------------------------------------------------
__global__ void __launch_bounds__(THREADS)
tile_kernel(const float* __restrict__ flow)
{
    const int cb   = blockIdx.x;          // 0..7
    const int rb   = blockIdx.y;          // 0..127
    const int t    = threadIdx.x;         // 0..255
    const int warp = t >> 5;
    const int lane = t & 31;
    const int row0 = rb * ROWS_PER_BLK;
    const int col0 = cb * COLS_PER_BLK;

    __shared__ float s_row[ROWS_PER_BLK][32];   // [row][warp*4 + sublane] 8 KB

    float4 c0 = make_float4(0.f, 0.f, 0.f, 0.f);

    const float4* base = reinterpret_cast<const float4*>(flow)
                         + (size_t)row0 * (N / 4) + (col0 / 4);

    #pragma unroll 4
    for (int r = 0; r < ROWS_PER_BLK; ++r) {
        float4 a = __ldcs(base + (size_t)r * (N / 4) + t);   // streaming

        c0.x += a.x; c0.y += a.y; c0.z += a.z; c0.w += a.w;

        // partial row reduce: 32 lanes -> 4 partials (3 shuffles)
        float s = (a.x + a.y) + (a.z + a.w);
        s += __shfl_xor_sync(0xffffffffu, s, 16);
        s += __shfl_xor_sync(0xffffffffu, s, 8);
        s += __shfl_xor_sync(0xffffffffu, s, 4);
        if (lane < 4) s_row[r][warp * 4 + lane] = s;
    }

    // Column partials -> fixed-point accumulators (spread-address REDG.64)
    {
        unsigned long long* cp = g_colsum + col0 + 4 * t;
        fx_add(cp + 0, c0.x);
        fx_add(cp + 1, c0.y);
        fx_add(cp + 2, c0.z);
        fx_add(cp + 3, c0.w);
    }

    __syncthreads();

    // Row fold: 4 threads per row (aligned 4-lane groups), 8 values each.
    {
        const int r = t >> 2;          // 0..63
        const int j = (t & 3) * 8;     // 0,8,16,24
        float s = ((s_row[r][j]     + s_row[r][j + 1]) +
                   (s_row[r][j + 2] + s_row[r][j + 3])) +
                  ((s_row[r][j + 4] + s_row[r][j + 5]) +
                   (s_row[r][j + 6] + s_row[r][j + 7]));
        s += __shfl_xor_sync(0xffffffffu, s, 2);
        s += __shfl_xor_sync(0xffffffffu, s, 1);
        if ((t & 3) == 0) fx_add(&g_rowsum[row0 + r], s);
    }
}

// ---------------------------------------------------------------------------
// Pass 2: single block, 1024 threads. Read 2x64 KB of accumulators (L2-hot),
// |rowsum - colsum| in fixed-point -> float, fixed-order tree reduce -> out.
// Re-zeroes the accumulators for the next graph replay.
// ---------------------------------------------------------------------------
__global__ void __launch_bounds__(1024)
epilogue_kernel(float* __restrict__ out)
{
    const int t    = threadIdx.x;
    const int warp = t >> 5;
    const int lane = t & 31;

    float v = 0.f;
    #pragma unroll
    for (int k = 0; k < N / 1024; ++k) {
        const int i = t + k * 1024;
        long long rs = (long long)g_rowsum[i];
        long long cs = (long long)g_colsum[i];
        v += fabsf((float)(rs - cs) * FXINV);
        g_rowsum[i] = 0ull;               // reset for next replay
        g_colsum[i] = 0ull;
    }

    v += __shfl_xor_sync(0xffffffffu, v, 16);
    v += __shfl_xor_sync(0xffffffffu, v, 8);
    v += __shfl_xor_sync(0xffffffffu, v, 4);
    v += __shfl_xor_sync(0xffffffffu, v, 2);
    v += __shfl_xor_sync(0xffffffffu, v, 1);

    __shared__ float sw[32];
    if (lane == 0) sw[warp] = v;
    __syncthreads();

    if (warp == 0) {
        float w = sw[lane];
        w += __shfl_xor_sync(0xffffffffu, w, 16);
        w += __shfl_xor_sync(0xffffffffu, w, 8);
        w += __shfl_xor_sync(0xffffffffu, w, 4);
        w += __shfl_xor_sync(0xffffffffu, w, 2);
        w += __shfl_xor_sync(0xffffffffu, w, 1);
        if (lane == 0) out[0] = w;
    }
}

extern "C" void kernel_launch(void* const* d_in, const int* in_sizes, int n_in,
                              void* d_out, int out_size)
{
    (void)in_sizes; (void)n_in; (void)out_size;
    const float* flow = (const float*)d_in[0];
    float* out = (float*)d_out;

    tile_kernel<<<dim3(CB, RB), THREADS>>>(flow);
    epilogue_kernel<<<1, 1024>>>(out);
}

// round 12
// speedup vs baseline: 1.1147x; 1.1147x over previous
#include <cuda_runtime.h>

#define N 8192
#define ROWS_PER_BLK 64
#define COLS_PER_BLK 1024
#define CB 8      /* column tiles: 8192/1024 */
#define RB 128    /* row tiles:    8192/64   */
#define THREADS 256
#define EBLK 128  /* epilogue blocks */

// Scratch (no device allocation allowed -> __device__ globals)
__device__ float g_rowpart[CB * N];     // [cb][row]  partial row sums (256 KB)
__device__ float g_colpart[RB * N];     // [rb][col]  partial col sums (4 MiB)
__device__ float g_blocksum[EBLK];
__device__ int   g_cnt_final;           // zero-init; self-resetting

// ---------------------------------------------------------------------------
// Pass 1 (UNCHANGED, proven 43.9us @ 78% DRAM): one block per 64x1024 tile
// -> 1024 blocks. Streaming single read of the 256 MiB matrix.
// ---------------------------------------------------------------------------
__global__ void __launch_bounds__(THREADS)
tile_kernel(const float* __restrict__ flow)
{
    const int cb   = blockIdx.x;          // 0..7
    const int rb   = blockIdx.y;          // 0..127
    const int t    = threadIdx.x;         // 0..255
    const int warp = t >> 5;
    const int lane = t & 31;
    const int row0 = rb * ROWS_PER_BLK;
    const int col0 = cb * COLS_PER_BLK;

    __shared__ float s_row[ROWS_PER_BLK][32];   // [row][warp*4 + sublane] 8 KB

    float4 c0 = make_float4(0.f, 0.f, 0.f, 0.f);

    const float4* base = reinterpret_cast<const float4*>(flow)
                         + (size_t)row0 * (N / 4) + (col0 / 4);

    #pragma unroll 4
    for (int r = 0; r < ROWS_PER_BLK; ++r) {
        float4 a = __ldcs(base + (size_t)r * (N / 4) + t);   // streaming

        c0.x += a.x; c0.y += a.y; c0.z += a.z; c0.w += a.w;

        // partial row reduce: 32 lanes -> 4 partials (3 shuffles)
        float s = (a.x + a.y) + (a.z + a.w);
        s += __shfl_xor_sync(0xffffffffu, s, 16);
        s += __shfl_xor_sync(0xffffffffu, s, 8);
        s += __shfl_xor_sync(0xffffffffu, s, 4);
        if (lane < 4) s_row[r][warp * 4 + lane] = s;
    }

    // Column partials: unique writer per (rb, col) -> plain store, no atomics
    reinterpret_cast<float4*>(g_colpart + (size_t)rb * N + col0)[t] = c0;

    __syncthreads();

    // Row fold: 4 threads per row (aligned 4-lane groups), 8 values each.
    {
        const int r = t >> 2;          // 0..63
        const int j = (t & 3) * 8;     // 0,8,16,24
        float s = ((s_row[r][j]     + s_row[r][j + 1]) +
                   (s_row[r][j + 2] + s_row[r][j + 3])) +
                  ((s_row[r][j + 4] + s_row[r][j + 5]) +
                   (s_row[r][j + 6] + s_row[r][j + 7]));
        s += __shfl_xor_sync(0xffffffffu, s, 2);
        s += __shfl_xor_sync(0xffffffffu, s, 1);
        if ((t & 3) == 0) g_rowpart[cb * N + row0 + r] = s;
    }
}

// ---------------------------------------------------------------------------
// Pass 2 (PDL epilogue, 128 blocks x 256 threads): blocks launch while the
// tile kernel drains; cudaGridDependencySynchronize() gates the reads.
// Block b owns 64 columns (16 float4-cols); 16 subs x 8 independent float4
// loads per thread. Deterministic fixed-order folds; integer-gated finish.
// ---------------------------------------------------------------------------
__global__ void __launch_bounds__(256)
epilogue_kernel(float* __restrict__ out)
{
    const int t   = threadIdx.x;          // 0..255
    const int fcl = t & 15;               // float4-col within block: 0..15
    const int sub = t >> 4;               // 0..15
    const int fc  = blockIdx.x * 16 + fcl;  // global float4-col: 0..2047

    const float4* cp = reinterpret_cast<const float4*>(g_colpart);

    cudaGridDependencySynchronize();      // wait for tile kernel's writes

    float4 cs = make_float4(0.f, 0.f, 0.f, 0.f);
    #pragma unroll
    for (int j = 0; j < RB / 16; ++j) {
        float4 a = cp[(size_t)(sub * (RB / 16) + j) * (N / 4) + fc];
        cs.x += a.x; cs.y += a.y; cs.z += a.z; cs.w += a.w;
    }

    __shared__ float4 s_part[16][17];     // [sub][fc] padded
    s_part[sub][fcl] = cs;
    __syncthreads();

    float v = 0.f;
    if (t < 16) {
        float4 tot = make_float4(0.f, 0.f, 0.f, 0.f);
        #pragma unroll
        for (int s2 = 0; s2 < 16; ++s2) {
            float4 a = s_part[s2][t];
            tot.x += a.x; tot.y += a.y; tot.z += a.z; tot.w += a.w;
        }
        const int myfc = blockIdx.x * 16 + t;
        float4 rs = make_float4(0.f, 0.f, 0.f, 0.f);
        #pragma unroll
        for (int cb = 0; cb < CB; ++cb) {
            float4 a = reinterpret_cast<const float4*>(g_rowpart + cb * N)[myfc];
            rs.x += a.x; rs.y += a.y; rs.z += a.z; rs.w += a.w;
        }
        v = (fabsf(rs.x - tot.x) + fabsf(rs.y - tot.y))
          + (fabsf(rs.z - tot.z) + fabsf(rs.w - tot.w));
    }

    if (t < 32) {
        v += __shfl_xor_sync(0xffffffffu, v, 8);
        v += __shfl_xor_sync(0xffffffffu, v, 4);
        v += __shfl_xor_sync(0xffffffffu, v, 2);
        v += __shfl_xor_sync(0xffffffffu, v, 1);
        if (t == 0) g_blocksum[blockIdx.x] = v;
    }

    // gate: globally-last block folds the 128 block sums
    __threadfence();
    __syncthreads();
    __shared__ int s_fin;
    if (t == 0) s_fin = (atomicAdd(&g_cnt_final, 1) == EBLK - 1);
    __syncthreads();
    if (!s_fin) return;
    __threadfence();

    float w = (t < EBLK) ? g_blocksum[t] : 0.f;
    w += __shfl_xor_sync(0xffffffffu, w, 16);
    w += __shfl_xor_sync(0xffffffffu, w, 8);
    w += __shfl_xor_sync(0xffffffffu, w, 4);
    w += __shfl_xor_sync(0xffffffffu, w, 2);
    w += __shfl_xor_sync(0xffffffffu, w, 1);

    __shared__ float sw[8];
    if ((t & 31) == 0) sw[t >> 5] = w;
    __syncthreads();

    if (t == 0) {
        float w2 = ((sw[0] + sw[1]) + (sw[2] + sw[3]))
                 + ((sw[4] + sw[5]) + (sw[6] + sw[7]));
        out[0] = w2;
        g_cnt_final = 0;   // reset for next graph replay
    }
}

extern "C" void kernel_launch(void* const* d_in, const int* in_sizes, int n_in,
                              void* d_out, int out_size)
{
    (void)in_sizes; (void)n_in; (void)out_size;
    const float* flow = (const float*)d_in[0];
    float* out = (float*)d_out;

    tile_kernel<<<dim3(CB, RB), THREADS>>>(flow);

    // Epilogue with Programmatic Dependent Launch: its blocks may launch
    // while tile_kernel drains; cudaGridDependencySynchronize() inside the
    // kernel enforces the data dependency.
    cudaLaunchConfig_t cfg = {};
    cfg.gridDim  = dim3(EBLK, 1, 1);
    cfg.blockDim = dim3(256, 1, 1);
    cudaLaunchAttribute attr[1];
    attr[0].id = cudaLaunchAttributeProgrammaticStreamSerialization;
    attr[0].val.programmaticStreamSerializationAllowed = 1;
    cfg.attrs = attr;
    cfg.numAttrs = 1;
    cudaLaunchKernelEx(&cfg, epilogue_kernel, out);
}

// round 13
// speedup vs baseline: 1.1572x; 1.0381x over previous
#include <cuda_runtime.h>

#define N 8192
#define ROWS_PER_BLK 256
#define COLS_PER_BLK 256
#define CB 32     /* column tiles: 8192/256 */
#define RB 32     /* row tiles:    8192/256 */
#define THREADS 256
#define EBLK 128  /* epilogue blocks */

// Scratch (no device allocation allowed -> __device__ globals)
__device__ float g_rowpart[CB * N];     // [cb][row]  partial row sums (1 MiB)
__device__ float g_colpart[RB * N];     // [rb][col]  partial col sums (1 MiB)
__device__ float g_blocksum[EBLK];
__device__ int   g_cnt_final;           // zero-init; self-resetting

// ---------------------------------------------------------------------------
// Pass 1: one block per 256x256 tile -> 1024 blocks (proven occupancy).
// Streaming single read of the 256 MiB matrix. Same per-iteration shape as
// the proven 43.9us loop: 1 LDG.128 -> col accum + 3-shuffle row partial.
// Thread layout: fc = t&63 (float4-col), rsub = t>>6 (row 4k+rsub).
// ---------------------------------------------------------------------------
__global__ void __launch_bounds__(THREADS)
tile_kernel(const float* __restrict__ flow)
{
    const int cb   = blockIdx.x;          // 0..31
    const int rb   = blockIdx.y;          // 0..31
    const int t    = threadIdx.x;         // 0..255
    const int lane = t & 31;
    const int fc   = t & 63;              // float4-col within tile
    const int rsub = t >> 6;              // 0..3
    const int half = (t >> 5) & 1;        // fc half within the row's 2 warps
    const int row0 = rb * ROWS_PER_BLK;
    const int col0 = cb * COLS_PER_BLK;

    __shared__ float  s_row[ROWS_PER_BLK][8];     // 8 partials per row, 8 KB
    __shared__ float4 s_cpart[4][64];             // [rsub][fc], 4 KB

    float4 c0 = make_float4(0.f, 0.f, 0.f, 0.f);

    const float4* base = reinterpret_cast<const float4*>(flow)
                         + (size_t)row0 * (N / 4) + (col0 / 4) + fc;

    #pragma unroll 4
    for (int k = 0; k < ROWS_PER_BLK / 4; ++k) {
        const int r = k * 4 + rsub;
        float4 a = __ldcs(base + (size_t)r * (N / 4));   // streaming

        c0.x += a.x; c0.y += a.y; c0.z += a.z; c0.w += a.w;

        // partial row reduce: 32 lanes -> 4 partials (3 shuffles)
        float s = (a.x + a.y) + (a.z + a.w);
        s += __shfl_xor_sync(0xffffffffu, s, 16);
        s += __shfl_xor_sync(0xffffffffu, s, 8);
        s += __shfl_xor_sync(0xffffffffu, s, 4);
        if (lane < 4) s_row[r][half * 4 + lane] = s;
    }

    s_cpart[rsub][fc] = c0;
    __syncthreads();

    // Column fold: threads 0..63 fold the 4 rsub partials per float4-col.
    if (t < 64) {
        float4 a0 = s_cpart[0][t], a1 = s_cpart[1][t];
        float4 a2 = s_cpart[2][t], a3 = s_cpart[3][t];
        float4 c;
        c.x = (a0.x + a1.x) + (a2.x + a3.x);
        c.y = (a0.y + a1.y) + (a2.y + a3.y);
        c.z = (a0.z + a1.z) + (a2.z + a3.z);
        c.w = (a0.w + a1.w) + (a2.w + a3.w);
        reinterpret_cast<float4*>(g_colpart + (size_t)rb * N + col0)[t] = c;
    }

    // Row fold: thread r folds its row's 8 partials (fixed order).
    {
        const float* p = s_row[t];
        float s = ((p[0] + p[1]) + (p[2] + p[3]))
                + ((p[4] + p[5]) + (p[6] + p[7]));
        g_rowpart[cb * N + row0 + t] = s;
    }
}

// ---------------------------------------------------------------------------
// Pass 2 (PDL epilogue, 128 blocks x 256 threads): block owns 64 columns
// (16 float4-cols). 16 subs: subs 0..7 fold colpart (4 independent float4
// loads each), subs 8..15 fold rowpart. 2 MiB covered in exactly one pass.
// smem fold -> |rowsum - colsum| -> warp reduce -> counter-gated finish.
// Fixed-order FP + integer atomics -> bitwise deterministic; self-resetting.
// ---------------------------------------------------------------------------
__global__ void __launch_bounds__(256)
epilogue_kernel(float* __restrict__ out)
{
    const int t   = threadIdx.x;            // 0..255
    const int fcl = t & 15;                 // float4-col within block
    const int sub = t >> 4;                 // 0..15
    const int fc  = blockIdx.x * 16 + fcl;  // global float4-col

    cudaGridDependencySynchronize();        // wait for tile kernel's writes

    const float4* cp = reinterpret_cast<const float4*>(g_colpart);
    const float4* rp = reinterpret_cast<const float4*>(g_rowpart);

    float4 acc = make_float4(0.f, 0.f, 0.f, 0.f);
    if (sub < 8) {
        #pragma unroll
        for (int j = 0; j < 4; ++j) {
            float4 a = cp[(size_t)(sub * 4 + j) * (N / 4) + fc];
            acc.x += a.x; acc.y += a.y; acc.z += a.z; acc.w += a.w;
        }
    } else {
        #pragma unroll
        for (int j = 0; j < 4; ++j) {
            float4 a = rp[(size_t)((sub - 8) * 4 + j) * (N / 4) + fc];
            acc.x += a.x; acc.y += a.y; acc.z += a.z; acc.w += a.w;
        }
    }

    __shared__ float4 s_part[16][17];       // [sub][fcl] padded
    s_part[sub][fcl] = acc;
    __syncthreads();

    float v = 0.f;
    if (t < 16) {
        float4 cs = make_float4(0.f, 0.f, 0.f, 0.f);
        float4 rs = make_float4(0.f, 0.f, 0.f, 0.f);
        #pragma unroll
        for (int s2 = 0; s2 < 8; ++s2) {
            float4 a = s_part[s2][t];
            cs.x += a.x; cs.y += a.y; cs.z += a.z; cs.w += a.w;
            float4 b = s_part[s2 + 8][t];
            rs.x += b.x; rs.y += b.y; rs.z += b.z; rs.w += b.w;
        }
        v = (fabsf(rs.x - cs.x) + fabsf(rs.y - cs.y))
          + (fabsf(rs.z - cs.z) + fabsf(rs.w - cs.w));
    }

    if (t < 32) {
        v += __shfl_xor_sync(0xffffffffu, v, 8);
        v += __shfl_xor_sync(0xffffffffu, v, 4);
        v += __shfl_xor_sync(0xffffffffu, v, 2);
        v += __shfl_xor_sync(0xffffffffu, v, 1);
        if (t == 0) g_blocksum[blockIdx.x] = v;
    }

    // gate: globally-last block folds the 128 block sums
    __threadfence();
    __syncthreads();
    __shared__ int s_fin;
    if (t == 0) s_fin = (atomicAdd(&g_cnt_final, 1) == EBLK - 1);
    __syncthreads();
    if (!s_fin) return;
    __threadfence();

    float w = (t < EBLK) ? g_blocksum[t] : 0.f;
    w += __shfl_xor_sync(0xffffffffu, w, 16);
    w += __shfl_xor_sync(0xffffffffu, w, 8);
    w += __shfl_xor_sync(0xffffffffu, w, 4);
    w += __shfl_xor_sync(0xffffffffu, w, 2);
    w += __shfl_xor_sync(0xffffffffu, w, 1);

    __shared__ float sw[8];
    if ((t & 31) == 0) sw[t >> 5] = w;
    __syncthreads();

    if (t == 0) {
        float w2 = ((sw[0] + sw[1]) + (sw[2] + sw[3]))
                 + ((sw[4] + sw[5]) + (sw[6] + sw[7]));
        out[0] = w2;
        g_cnt_final = 0;   // reset for next graph replay
    }
}

extern "C" void kernel_launch(void* const* d_in, const int* in_sizes, int n_in,
                              void* d_out, int out_size)
{
    (void)in_sizes; (void)n_in; (void)out_size;
    const float* flow = (const float*)d_in[0];
    float* out = (float*)d_out;

    tile_kernel<<<dim3(CB, RB), THREADS>>>(flow);

    // Epilogue with Programmatic Dependent Launch (proven capturable).
    cudaLaunchConfig_t cfg = {};
    cfg.gridDim  = dim3(EBLK, 1, 1);
    cfg.blockDim = dim3(256, 1, 1);
    cudaLaunchAttribute attr[1];
    attr[0].id = cudaLaunchAttributeProgrammaticStreamSerialization;
    attr[0].val.programmaticStreamSerializationAllowed = 1;
    cfg.attrs = attr;
    cfg.numAttrs = 1;
    cudaLaunchKernelEx(&cfg, epilogue_kernel, out);
}